// round 1
// baseline (speedup 1.0000x reference)
#include <cuda_runtime.h>
#include <cuda_bf16.h>
#include <cstdint>

#define SDIM 2304
#define CDIM 1280
#define NHEAD 20
#define DHEAD 64
#define SS ((size_t)SDIM * SDIM)

// ---------------- static scratch (no allocations allowed) ----------------
__device__ float g_Q[(size_t)NHEAD * SDIM * DHEAD];   // 11.8 MB
__device__ float g_K[(size_t)NHEAD * SDIM * DHEAD];
__device__ float g_V[(size_t)NHEAD * SDIM * DHEAD];
__device__ float g_Ctx[(size_t)SDIM * CDIM];          // 11.8 MB
__device__ float g_P[(size_t)NHEAD * SDIM * SDIM];    // 425 MB
__device__ unsigned char g_mask[(size_t)SDIM * SDIM]; // 5.3 MB
__device__ int g_mask_mode;                           // 1 = 32-bit words, 2 = bytes

// ---------------- mask dtype detection + normalization ----------------
__global__ void detect_mask_kernel(const unsigned int* __restrict__ m) {
    if (threadIdx.x != 0) return;
    bool all01 = true, allf = true;
    #pragma unroll 1
    for (int i = 0; i < 256; i++) {
        unsigned int w = m[i * 997 + 1];
        if (!(w == 0u || w == 1u)) all01 = false;
        if (!(w == 0u || w == 0x3F800000u)) allf = false;
    }
    g_mask_mode = (all01 || allf) ? 1 : 2;
}

__global__ void norm_mask_kernel(const void* __restrict__ m) {
    size_t i = (size_t)blockIdx.x * 256 + threadIdx.x;
    if (i >= SS) return;
    if (g_mask_mode == 1) {
        g_mask[i] = (((const unsigned int*)m)[i] != 0u) ? 1 : 0;
    } else {
        g_mask[i] = (((const unsigned char*)m)[i] != 0) ? 1 : 0;
    }
}

// ---------------- generic 128x128x8 SGEMM: projections ----------------
// Y = X[SDIM,CDIM] @ W[CDIM,CDIM]; output written head-major [H][S][64]
__global__ __launch_bounds__(256) void gemm_proj_kernel(
    const float* __restrict__ X, const float* __restrict__ W,
    float* __restrict__ Yhead)
{
    __shared__ float As[8][128];
    __shared__ float Bs[8][128];
    const int tid = threadIdx.x;
    const int mBase = blockIdx.y * 128;
    const int nBase = blockIdx.x * 128;

    float c[8][8];
    #pragma unroll
    for (int i = 0; i < 8; i++)
        #pragma unroll
        for (int j = 0; j < 8; j++) c[i][j] = 0.f;

    const int arow = tid >> 1;          // 0..127
    const int acol = (tid & 1) * 4;     // 0 or 4
    const int brow = tid >> 5;          // 0..7
    const int bcol = (tid & 31) * 4;    // 0..124

    const float* Xp = X + (size_t)(mBase + arow) * CDIM + acol;
    const float* Wp = W + (size_t)brow * CDIM + nBase + bcol;

    const int tr = (tid >> 4) * 8;
    const int tc = (tid & 15) * 8;

    for (int kt = 0; kt < CDIM; kt += 8) {
        float4 av = *(const float4*)(Xp + kt);
        float4 bv = *(const float4*)(Wp + (size_t)kt * CDIM);
        As[acol + 0][arow] = av.x; As[acol + 1][arow] = av.y;
        As[acol + 2][arow] = av.z; As[acol + 3][arow] = av.w;
        *(float4*)&Bs[brow][bcol] = bv;
        __syncthreads();
        #pragma unroll
        for (int k = 0; k < 8; k++) {
            float a[8], b[8];
            *(float4*)(a)     = *(const float4*)&As[k][tr];
            *(float4*)(a + 4) = *(const float4*)&As[k][tr + 4];
            *(float4*)(b)     = *(const float4*)&Bs[k][tc];
            *(float4*)(b + 4) = *(const float4*)&Bs[k][tc + 4];
            #pragma unroll
            for (int i = 0; i < 8; i++)
                #pragma unroll
                for (int j = 0; j < 8; j++) c[i][j] = fmaf(a[i], b[j], c[i][j]);
        }
        __syncthreads();
    }
    #pragma unroll
    for (int i = 0; i < 8; i++) {
        int m = mBase + tr + i;
        #pragma unroll
        for (int j = 0; j < 8; j++) {
            int n = nBase + tc + j;
            int h = n >> 6, dd = n & 63;
            Yhead[((size_t)h * SDIM + m) * DHEAD + dd] = c[i][j];
        }
    }
}

// ---------------- final projection with bias: Y = X @ W + b ----------------
__global__ __launch_bounds__(256) void gemm_out_kernel(
    const float* __restrict__ X, const float* __restrict__ W,
    const float* __restrict__ bias, float* __restrict__ Y)
{
    __shared__ float As[8][128];
    __shared__ float Bs[8][128];
    const int tid = threadIdx.x;
    const int mBase = blockIdx.y * 128;
    const int nBase = blockIdx.x * 128;

    float c[8][8];
    #pragma unroll
    for (int i = 0; i < 8; i++)
        #pragma unroll
        for (int j = 0; j < 8; j++) c[i][j] = 0.f;

    const int arow = tid >> 1;
    const int acol = (tid & 1) * 4;
    const int brow = tid >> 5;
    const int bcol = (tid & 31) * 4;

    const float* Xp = X + (size_t)(mBase + arow) * CDIM + acol;
    const float* Wp = W + (size_t)brow * CDIM + nBase + bcol;

    const int tr = (tid >> 4) * 8;
    const int tc = (tid & 15) * 8;

    for (int kt = 0; kt < CDIM; kt += 8) {
        float4 av = *(const float4*)(Xp + kt);
        float4 bv = *(const float4*)(Wp + (size_t)kt * CDIM);
        As[acol + 0][arow] = av.x; As[acol + 1][arow] = av.y;
        As[acol + 2][arow] = av.z; As[acol + 3][arow] = av.w;
        *(float4*)&Bs[brow][bcol] = bv;
        __syncthreads();
        #pragma unroll
        for (int k = 0; k < 8; k++) {
            float a[8], b[8];
            *(float4*)(a)     = *(const float4*)&As[k][tr];
            *(float4*)(a + 4) = *(const float4*)&As[k][tr + 4];
            *(float4*)(b)     = *(const float4*)&Bs[k][tc];
            *(float4*)(b + 4) = *(const float4*)&Bs[k][tc + 4];
            #pragma unroll
            for (int i = 0; i < 8; i++)
                #pragma unroll
                for (int j = 0; j < 8; j++) c[i][j] = fmaf(a[i], b[j], c[i][j]);
        }
        __syncthreads();
    }
    #pragma unroll
    for (int i = 0; i < 8; i++) {
        int m = mBase + tr + i;
        #pragma unroll
        for (int j = 0; j < 8; j++) {
            int n = nBase + tc + j;
            Y[(size_t)m * CDIM + n] = c[i][j] + bias[n];
        }
    }
}

// ---------------- scores: P[h] = scale * Q_h @ K_h^T, masked ----------------
__global__ __launch_bounds__(256) void gemm_scores_kernel(float scaleV) {
    const int h = blockIdx.z;
    const float* Q = g_Q + (size_t)h * SDIM * DHEAD;
    const float* K = g_K + (size_t)h * SDIM * DHEAD;
    float* P = g_P + (size_t)h * SS;

    __shared__ float As[8][128];
    __shared__ float Bs[8][128];
    const int tid = threadIdx.x;
    const int mBase = blockIdx.y * 128;  // query rows
    const int nBase = blockIdx.x * 128;  // key rows

    float c[8][8];
    #pragma unroll
    for (int i = 0; i < 8; i++)
        #pragma unroll
        for (int j = 0; j < 8; j++) c[i][j] = 0.f;

    const int arow = tid >> 1;
    const int acol = (tid & 1) * 4;
    const float* Qp = Q + (size_t)(mBase + arow) * DHEAD + acol;
    const float* Kp = K + (size_t)(nBase + arow) * DHEAD + acol;

    const int tr = (tid >> 4) * 8;
    const int tc = (tid & 15) * 8;

    #pragma unroll
    for (int kt = 0; kt < DHEAD; kt += 8) {
        float4 av = *(const float4*)(Qp + kt);
        float4 bv = *(const float4*)(Kp + kt);
        As[acol + 0][arow] = av.x; As[acol + 1][arow] = av.y;
        As[acol + 2][arow] = av.z; As[acol + 3][arow] = av.w;
        Bs[acol + 0][arow] = bv.x; Bs[acol + 1][arow] = bv.y;
        Bs[acol + 2][arow] = bv.z; Bs[acol + 3][arow] = bv.w;
        __syncthreads();
        #pragma unroll
        for (int k = 0; k < 8; k++) {
            float a[8], b[8];
            *(float4*)(a)     = *(const float4*)&As[k][tr];
            *(float4*)(a + 4) = *(const float4*)&As[k][tr + 4];
            *(float4*)(b)     = *(const float4*)&Bs[k][tc];
            *(float4*)(b + 4) = *(const float4*)&Bs[k][tc + 4];
            #pragma unroll
            for (int i = 0; i < 8; i++)
                #pragma unroll
                for (int j = 0; j < 8; j++) c[i][j] = fmaf(a[i], b[j], c[i][j]);
        }
        __syncthreads();
    }
    #pragma unroll
    for (int i = 0; i < 8; i++) {
        int m = mBase + tr + i;
        const unsigned char* mrow = g_mask + (size_t)m * SDIM;
        float* prow = P + (size_t)m * SDIM;
        #pragma unroll
        for (int j = 0; j < 8; j++) {
            int n = nBase + tc + j;
            float v = c[i][j] * scaleV;
            if (!mrow[n]) v = -1e30f;
            prow[n] = v;
        }
    }
}

// ---------------- softmax over each row of P (length 2304) ----------------
__global__ __launch_bounds__(256) void softmax_kernel() {
    const int q = blockIdx.x;
    const int h = blockIdx.y;
    float* row = g_P + ((size_t)h * SDIM + q) * SDIM;
    const int tid = threadIdx.x;

    float v[9];
    float mx = -1e30f;
    #pragma unroll
    for (int i = 0; i < 9; i++) {
        v[i] = row[tid + i * 256];
        mx = fmaxf(mx, v[i]);
    }
    __shared__ float red[256];
    red[tid] = mx; __syncthreads();
    #pragma unroll
    for (int s = 128; s > 0; s >>= 1) {
        if (tid < s) red[tid] = fmaxf(red[tid], red[tid + s]);
        __syncthreads();
    }
    mx = red[0]; __syncthreads();

    float sum = 0.f;
    #pragma unroll
    for (int i = 0; i < 9; i++) {
        v[i] = __expf(v[i] - mx);
        sum += v[i];
    }
    red[tid] = sum; __syncthreads();
    #pragma unroll
    for (int s = 128; s > 0; s >>= 1) {
        if (tid < s) red[tid] += red[tid + s];
        __syncthreads();
    }
    float inv = 1.f / red[0];
    #pragma unroll
    for (int i = 0; i < 9; i++) row[tid + i * 256] = v[i] * inv;
}

// ---------------- PV: Ctx[:, h*64:(h+1)*64] = P_h @ V_h ----------------
__global__ __launch_bounds__(256) void gemm_pv_kernel() {
    const int h = blockIdx.z;
    const int mBase = blockIdx.x * 128;
    const float* P = g_P + (size_t)h * SS;
    const float* V = g_V + (size_t)h * SDIM * DHEAD;

    __shared__ float Ps[16][128];
    __shared__ float Vs[16][64];
    const int tid = threadIdx.x;

    float c[8][4];
    #pragma unroll
    for (int i = 0; i < 8; i++)
        #pragma unroll
        for (int j = 0; j < 4; j++) c[i][j] = 0.f;

    const int prow = tid >> 1;          // 0..127
    const int pcol = (tid & 1) * 8;     // 0 or 8
    const int vrow = tid >> 4;          // 0..15
    const int vcol = (tid & 15) * 4;    // 0..60

    const float* Pp = P + (size_t)(mBase + prow) * SDIM + pcol;
    const float* Vp = V + (size_t)vrow * DHEAD + vcol;

    const int tr = (tid >> 4) * 8;      // 0..120
    const int tc = (tid & 15) * 4;      // 0..60

    for (int kt = 0; kt < SDIM; kt += 16) {
        float4 p0 = *(const float4*)(Pp + kt);
        float4 p1 = *(const float4*)(Pp + kt + 4);
        Ps[pcol + 0][prow] = p0.x; Ps[pcol + 1][prow] = p0.y;
        Ps[pcol + 2][prow] = p0.z; Ps[pcol + 3][prow] = p0.w;
        Ps[pcol + 4][prow] = p1.x; Ps[pcol + 5][prow] = p1.y;
        Ps[pcol + 6][prow] = p1.z; Ps[pcol + 7][prow] = p1.w;
        float4 vv = *(const float4*)(Vp + (size_t)kt * DHEAD);
        *(float4*)&Vs[vrow][vcol] = vv;
        __syncthreads();
        #pragma unroll
        for (int k = 0; k < 16; k++) {
            float a[8], b[4];
            *(float4*)(a)     = *(const float4*)&Ps[k][tr];
            *(float4*)(a + 4) = *(const float4*)&Ps[k][tr + 4];
            *(float4*)(b)     = *(const float4*)&Vs[k][tc];
            #pragma unroll
            for (int i = 0; i < 8; i++)
                #pragma unroll
                for (int j = 0; j < 4; j++) c[i][j] = fmaf(a[i], b[j], c[i][j]);
        }
        __syncthreads();
    }
    #pragma unroll
    for (int i = 0; i < 8; i++) {
        int m = mBase + tr + i;
        #pragma unroll
        for (int j = 0; j < 4; j++) {
            g_Ctx[(size_t)m * CDIM + h * DHEAD + tc + j] = c[i][j];
        }
    }
}

// ---------------- launcher ----------------
extern "C" void kernel_launch(void* const* d_in, const int* in_sizes, int n_in,
                              void* d_out, int out_size) {
    const float* hidden = (const float*)d_in[0];
    const void*  mask   = d_in[1];
    const float* Wq     = (const float*)d_in[2];
    const float* Wk     = (const float*)d_in[3];
    const float* Wv     = (const float*)d_in[4];
    const float* Wo     = (const float*)d_in[5];
    const float* bo     = (const float*)d_in[6];
    float* out = (float*)d_out;

    float* dQ;   cudaGetSymbolAddress((void**)&dQ,   g_Q);
    float* dK;   cudaGetSymbolAddress((void**)&dK,   g_K);
    float* dV;   cudaGetSymbolAddress((void**)&dV,   g_V);
    float* dCtx; cudaGetSymbolAddress((void**)&dCtx, g_Ctx);

    // 1) mask dtype detect + normalize
    detect_mask_kernel<<<1, 32>>>((const unsigned int*)mask);
    norm_mask_kernel<<<(int)((SS + 255) / 256), 256>>>(mask);

    // 2) Q/K/V projections (head-major outputs)
    dim3 gProj(CDIM / 128, SDIM / 128);
    gemm_proj_kernel<<<gProj, 256>>>(hidden, Wq, dQ);
    gemm_proj_kernel<<<gProj, 256>>>(hidden, Wk, dK);
    gemm_proj_kernel<<<gProj, 256>>>(hidden, Wv, dV);

    // 3) scores + mask
    dim3 gSc(SDIM / 128, SDIM / 128, NHEAD);
    gemm_scores_kernel<<<gSc, 256>>>(0.125f);  // 1/sqrt(64)

    // 4) softmax
    dim3 gSm(SDIM, NHEAD);
    softmax_kernel<<<gSm, 256>>>();

    // 5) PV
    dim3 gPv(SDIM / 128, 1, NHEAD);
    gemm_pv_kernel<<<gPv, 256>>>();

    // 6) output projection + bias
    dim3 gOut(CDIM / 128, SDIM / 128);
    gemm_out_kernel<<<gOut, 256>>>(dCtx, Wo, bo, out);
}